// round 3
// baseline (speedup 1.0000x reference)
#include <cuda_runtime.h>

#define NPTS   4096
#define BATCH  8
#define NSAMP  32
#define R2     0.0625f
#define QPW    4
#define GD     40
#define GD3    (GD*GD*GD)
#define CAP    64

// Preprocessed points: (2x, 2y, 2z, -(x^2+y^2+z^2))
__device__ float4 xyz4g[BATCH * NPTS];
__device__ int    pointCell[BATCH * NPTS];
__device__ int    cellCnt [BATCH * GD3];
__device__ int    cellStart[BATCH * GD3];
__device__ int    cellFill [BATCH * GD3];
__device__ int    sortedIdx[BATCH * NPTS];

__device__ __forceinline__ int cellc(float v) {
    int c = (int)floorf((v + 5.0f) * 4.0f);
    return min(GD - 1, max(0, c));
}

__global__ void lse_zero() {
    int i = blockIdx.x * blockDim.x + threadIdx.x;
    if (i < BATCH * GD3) cellCnt[i] = 0;
}

__global__ void lse_prep(const float* __restrict__ xyz) {
    int i = blockIdx.x * blockDim.x + threadIdx.x;
    if (i >= BATCH * NPTS) return;
    float x = xyz[3*i], y = xyz[3*i+1], z = xyz[3*i+2];
    float sq = fmaf(x, x, fmaf(y, y, z * z));
    xyz4g[i] = make_float4(2.0f*x, 2.0f*y, 2.0f*z, -sq);
    int cid = (cellc(z) * GD + cellc(y)) * GD + cellc(x);
    pointCell[i] = cid;
    atomicAdd(&cellCnt[(i >> 12) * GD3 + cid], 1);
}

// One CTA per batch: exclusive scan of 64000 cell counts.
__global__ __launch_bounds__(1024) void lse_scan() {
    __shared__ int part[1024];
    int b = blockIdx.x, t = threadIdx.x;
    const int CH = (GD3 + 1023) / 1024;   // 63
    int s = t * CH, e = min(s + CH, GD3);
    const int* cc = cellCnt + b * GD3;
    int sum = 0;
    for (int i = s; i < e; i++) sum += cc[i];
    part[t] = sum;
    __syncthreads();
    for (int d = 1; d < 1024; d <<= 1) {
        int v = (t >= d) ? part[t - d] : 0;
        __syncthreads();
        part[t] += v;
        __syncthreads();
    }
    int run = (t > 0) ? part[t - 1] : 0;
    int* cs = cellStart + b * GD3;
    int* cf = cellFill  + b * GD3;
    for (int i = s; i < e; i++) {
        cs[i] = run; cf[i] = run;
        run += cc[i];
    }
}

__global__ void lse_scatter() {
    int i = blockIdx.x * blockDim.x + threadIdx.x;
    if (i >= BATCH * NPTS) return;
    int b = i >> 12;
    int pos = atomicAdd(&cellFill[b * GD3 + pointCell[i]], 1);
    sortedIdx[b * NPTS + pos] = i & (NPTS - 1);
}

// 512 threads = 16 warps; each warp owns 4 query points.
__global__ __launch_bounds__(512, 1) void lse_main_kernel(
    const float* __restrict__ w1, const float* __restrict__ b1,
    const float* __restrict__ w2, const float* __restrict__ b2,
    float* __restrict__ out)
{
    __shared__ float w2t[32 * 65];
    __shared__ int   nbr[16][QPW][CAP];
    __shared__ int   cE[16][32];     // inclusive prefix of 27-cell counts
    __shared__ int   cA[16][32];     // cellStart - exclusive prefix

    const int tid = threadIdx.x;
    for (int t = tid; t < 64 * 32; t += 512) {
        int o = t >> 5, i = t & 31;
        w2t[i * 65 + o] = w2[t];
    }
    __syncthreads();

    const int lane = tid & 31;
    const int w    = tid >> 5;
    const int b    = blockIdx.x >> 6;
    const int nbase = ((blockIdx.x & 63) << 6) + (w << 2);

    const float4* __restrict__ P   = xyz4g    + b * NPTS;
    const int* __restrict__ csG    = cellStart + b * GD3;
    const int* __restrict__ ccG    = cellCnt   + b * GD3;
    const int* __restrict__ sIdx   = sortedIdx + b * NPTS;

    float xn[QPW], yn[QPW], zn[QPW], sv[QPW];
    int cnt[QPW];
    #pragma unroll
    for (int q = 0; q < QPW; q++) {
        float4 qn = P[nbase + q];
        xn[q] = 0.5f * qn.x;          // exact x_n
        yn[q] = 0.5f * qn.y;
        zn[q] = 0.5f * qn.z;
        sv[q] = -qn.w - R2;           // sq_n - R^2
        cnt[q] = 0;
    }

    // lane -> one of 27 neighbor-cell offsets
    const int dxl = lane % 3 - 1;
    const int dyl = (lane / 3) % 3 - 1;
    const int dzl = lane / 9 - 1;

    // ---- Phase 1: grid-pruned ball query
    for (int q = 0; q < QPW; q++) {
        int cx = cellc(xn[q]), cy = cellc(yn[q]), cz = cellc(zn[q]);
        int gx = cx + dxl, gy = cy + dyl, gz = cz + dzl;
        bool cv = (lane < 27) & (gx >= 0) & (gx < GD) & (gy >= 0) & (gy < GD)
                              & (gz >= 0) & (gz < GD);
        int cs = 0, cc = 0;
        if (cv) {
            int cid = (gz * GD + gy) * GD + gx;
            cs = csG[cid];
            cc = ccG[cid];
        }
        // warp inclusive scan of cc
        int inc = cc;
        #pragma unroll
        for (int d = 1; d < 32; d <<= 1) {
            int u = __shfl_up_sync(0xffffffffu, inc, d);
            if (lane >= d) inc += u;
        }
        int T = __shfl_sync(0xffffffffu, inc, 31);
        cE[w][lane] = inc;            // nondecreasing; lanes >= 27 hold T
        cA[w][lane] = cs - (inc - cc);
        __syncwarp();

        int iters = (T + 31) >> 5;
        for (int it = 0; it < iters; it++) {
            int t = (it << 5) + lane;
            bool act = t < T;
            // rank = # entries <= t  (branchless lower-bound over sorted 32)
            int j = 0;
            if (cE[w][j + 15] <= t) j += 16;
            if (cE[w][j + 7]  <= t) j += 8;
            if (cE[w][j + 3]  <= t) j += 4;
            if (cE[w][j + 1]  <= t) j += 2;
            if (cE[w][j]      <= t) j += 1;
            int m = 0;
            if (act) m = sIdx[cA[w][j] + t];
            float4 p = P[m];
            float acc = fmaf(p.x, xn[q], fmaf(p.y, yn[q], fmaf(p.z, zn[q], p.w)));
            bool v = act && (acc > sv[q]);
            unsigned msk = __ballot_sync(0xffffffffu, v);
            if (v) {
                int pos = cnt[q] + __popc(msk & ((1u << lane) - 1u));
                if (pos < CAP) nbr[w][q][pos] = m;
            }
            cnt[q] += __popc(msk);
        }
        __syncwarp();   // cE/cA reused by next q
    }

    // ---- Rare slow path: cnt > 32 -> keep 32 smallest original indices
    #pragma unroll
    for (int q = 0; q < QPW; q++) {
        if (cnt[q] > NSAMP) {                       // warp-uniform
            int c = min(cnt[q], CAP);
            int v0 = (lane      < c) ? nbr[w][q][lane]      : 0x7fffffff;
            int v1 = (lane + 32 < c) ? nbr[w][q][lane + 32] : 0x7fffffff;
            for (int j = 0; j < NSAMP; j++) {
                int mn = min(v0, v1);
                #pragma unroll
                for (int d = 16; d >= 1; d >>= 1)
                    mn = min(mn, __shfl_xor_sync(0xffffffffu, mn, d));
                if (lane == 0) nbr[w][q][j] = mn;
                if (v0 == mn) v0 = 0x7fffffff;
                else if (v1 == mn) v1 = 0x7fffffff;
            }
            __syncwarp();
            cnt[q] = NSAMP;
        }
    }

    // ---- Per-lane MLP weights (loaded after the scan)
    const float w1x = w1[3 * lane + 0];
    const float w1y = w1[3 * lane + 1];
    const float w1z = w1[3 * lane + 2];
    const float b1v = b1[lane];
    const float b20 = b2[lane];
    const float b21 = b2[lane + 32];

    float w2a[32], w2b[32];
    #pragma unroll
    for (int i = 0; i < 32; i++) {
        w2a[i] = w2t[i * 65 + lane];
        w2b[i] = w2t[i * 65 + lane + 32];
    }

    // ---- Phase 2: MLP + max pool (warp-uniform loops)
    #pragma unroll
    for (int q = 0; q < QPW; q++) {
        const int k = cnt[q];                       // 1..32
        const float qx = xn[q], qy = yn[q], qz = zn[q];
        float p0 = 0.0f, p1 = 0.0f;
        for (int j = 0; j < k; j++) {
            int m = nbr[w][q][j];
            float4 p = P[m];                        // uniform -> broadcast
            float rx = fmaf(0.5f, p.x, -qx);        // exact fl(x_m - x_n)
            float ry = fmaf(0.5f, p.y, -qy);
            float rz = fmaf(0.5f, p.z, -qz);
            float h = fmaf(w1x, rx, fmaf(w1y, ry, fmaf(w1z, rz, b1v)));
            h = fmaxf(h, 0.0f);
            float a0 = b20, a1 = b21;
            #pragma unroll
            for (int i = 0; i < 32; i++) {
                float hi = __shfl_sync(0xffffffffu, h, i);
                a0 = fmaf(w2a[i], hi, a0);
                a1 = fmaf(w2b[i], hi, a1);
            }
            p0 = fmaxf(p0, fmaxf(a0, 0.0f));
            p1 = fmaxf(p1, fmaxf(a1, 0.0f));
        }
        float* o = out + (size_t)(b * NPTS + nbase + q) * 65;
        o[lane]      = p0;
        o[lane + 32] = p1;
        if (lane == 0) o[64] = (float)k * (1.0f / 64.0f);
    }
}

extern "C" void kernel_launch(void* const* d_in, const int* in_sizes, int n_in,
                              void* d_out, int out_size) {
    const float* xyz = (const float*)d_in[0];
    const float* w1  = (const float*)d_in[1];
    const float* b1  = (const float*)d_in[2];
    const float* w2  = (const float*)d_in[3];
    const float* b2  = (const float*)d_in[4];
    float* out = (float*)d_out;

    lse_zero   <<<(BATCH * GD3 + 255) / 256, 256>>>();
    lse_prep   <<<(BATCH * NPTS + 255) / 256, 256>>>(xyz);
    lse_scan   <<<BATCH, 1024>>>();
    lse_scatter<<<(BATCH * NPTS + 255) / 256, 256>>>();
    lse_main_kernel<<<BATCH * (NPTS / (QPW * 16)), 512>>>(w1, b1, w2, b2, out);
}

// round 4
// speedup vs baseline: 1.7876x; 1.7876x over previous
#include <cuda_runtime.h>

#define NPTS   4096
#define BATCH  8
#define NSAMP  32
#define R2     0.0625f
#define QPW    4
#define GD     28
#define GD3    (GD*GD*GD)
#define CAP    64
#define JT     4       // neighbor tile for phase-2 h staging

// Preprocessed points: (2x, 2y, 2z, -(x^2+y^2+z^2))
__device__ float4 xyz4g[BATCH * NPTS];
__device__ int    pointCell[BATCH * NPTS];
__device__ int    cellCnt [BATCH * GD3];
__device__ int    cellStart[BATCH * GD3];
__device__ int    cellFill [BATCH * GD3];
__device__ int    sortedIdx[BATCH * NPTS];
__device__ int    baseCtr[BATCH];

__device__ __forceinline__ int cellc(float v) {
    int c = (int)floorf((v + 3.5f) * 4.0f);
    return min(GD - 1, max(0, c));
}

__device__ __forceinline__ unsigned long long pk2(float lo, float hi) {
    unsigned long long r;
    asm("mov.b64 %0, {%1, %2};" : "=l"(r) : "f"(lo), "f"(hi));
    return r;
}
__device__ __forceinline__ void ffma2(unsigned long long& d,
                                      unsigned long long a, unsigned long long b) {
    asm("fma.rn.f32x2 %0, %1, %2, %0;" : "+l"(d) : "l"(a), "l"(b));
}

__global__ void lse_zero() {
    int i = blockIdx.x * blockDim.x + threadIdx.x;
    if (i < BATCH * GD3) cellCnt[i] = 0;
    if (i < BATCH) baseCtr[i] = 0;
}

__global__ void lse_prep(const float* __restrict__ xyz) {
    int i = blockIdx.x * blockDim.x + threadIdx.x;
    if (i >= BATCH * NPTS) return;
    float x = xyz[3*i], y = xyz[3*i+1], z = xyz[3*i+2];
    float sq = fmaf(x, x, fmaf(y, y, z * z));
    xyz4g[i] = make_float4(2.0f*x, 2.0f*y, 2.0f*z, -sq);
    int cid = (cellc(z) * GD + cellc(y)) * GD + cellc(x);
    pointCell[i] = cid;
    atomicAdd(&cellCnt[(i >> 12) * GD3 + cid], 1);
}

// Parallel bump allocation: any disjoint per-cell layout is valid.
__global__ void lse_alloc() {
    int i = blockIdx.x * blockDim.x + threadIdx.x;
    if (i >= BATCH * GD3) return;
    int c = cellCnt[i];
    if (c > 0) {
        int s = atomicAdd(&baseCtr[i / GD3], c);
        cellStart[i] = s;
        cellFill[i]  = s;
    }
}

__global__ void lse_scatter() {
    int i = blockIdx.x * blockDim.x + threadIdx.x;
    if (i >= BATCH * NPTS) return;
    int b = i >> 12;
    int pos = atomicAdd(&cellFill[b * GD3 + pointCell[i]], 1);
    sortedIdx[b * NPTS + pos] = i & (NPTS - 1);
}

// 512 threads = 16 warps; each warp owns 4 query points.
__global__ __launch_bounds__(512, 1) void lse_main_kernel(
    const float* __restrict__ w1, const float* __restrict__ b1,
    const float* __restrict__ w2, const float* __restrict__ b2,
    float* __restrict__ out)
{
    __shared__ float  w2t[32 * 65];
    __shared__ int    nbr[16][QPW][CAP];
    __shared__ int    cE[16][32];
    __shared__ int    cA[16][32];
    __shared__ __align__(16) float hbuf[16][JT * 64];  // duplicated h, 16B aligned

    const int tid = threadIdx.x;
    for (int t = tid; t < 64 * 32; t += 512) {
        int o = t >> 5, i = t & 31;
        w2t[i * 65 + o] = w2[t];
    }
    __syncthreads();

    const int lane = tid & 31;
    const int w    = tid >> 5;
    const int b    = blockIdx.x >> 6;
    const int nbase = ((blockIdx.x & 63) << 6) + (w << 2);

    const float4* __restrict__ P  = xyz4g     + b * NPTS;
    const int* __restrict__ csG   = cellStart + b * GD3;
    const int* __restrict__ ccG   = cellCnt   + b * GD3;
    const int* __restrict__ sIdx  = sortedIdx + b * NPTS;

    float xn[QPW], yn[QPW], zn[QPW], sv[QPW];
    int cnt[QPW];
    #pragma unroll
    for (int q = 0; q < QPW; q++) {
        float4 qn = P[nbase + q];
        xn[q] = 0.5f * qn.x;          // exact x_n
        yn[q] = 0.5f * qn.y;
        zn[q] = 0.5f * qn.z;
        sv[q] = -qn.w - R2;           // sq_n - R^2
        cnt[q] = 0;
    }

    const int dxl = lane % 3 - 1;
    const int dyl = (lane / 3) % 3 - 1;
    const int dzl = lane / 9 - 1;

    // ---- Phase 1: grid-pruned ball query
    for (int q = 0; q < QPW; q++) {
        int gx = cellc(xn[q]) + dxl;
        int gy = cellc(yn[q]) + dyl;
        int gz = cellc(zn[q]) + dzl;
        bool cv = (lane < 27) & (gx >= 0) & (gx < GD) & (gy >= 0) & (gy < GD)
                              & (gz >= 0) & (gz < GD);
        int cs = 0, cc = 0;
        if (cv) {
            int cid = (gz * GD + gy) * GD + gx;
            cs = csG[cid];
            cc = ccG[cid];
        }
        int inc = cc;
        #pragma unroll
        for (int d = 1; d < 32; d <<= 1) {
            int u = __shfl_up_sync(0xffffffffu, inc, d);
            if (lane >= d) inc += u;
        }
        int T = __shfl_sync(0xffffffffu, inc, 31);
        cE[w][lane] = inc;            // nondecreasing; lanes >= 27 hold T
        cA[w][lane] = cs - (inc - cc);
        __syncwarp();

        int iters = (T + 31) >> 5;
        for (int it = 0; it < iters; it++) {
            int t = (it << 5) + lane;
            bool act = t < T;
            int j = 0;
            if (cE[w][j + 15] <= t) j += 16;
            if (cE[w][j + 7]  <= t) j += 8;
            if (cE[w][j + 3]  <= t) j += 4;
            if (cE[w][j + 1]  <= t) j += 2;
            if (cE[w][j]      <= t) j += 1;
            int m = 0;
            if (act) m = sIdx[cA[w][j] + t];
            float4 p = P[m];
            float acc = fmaf(p.x, xn[q], fmaf(p.y, yn[q], fmaf(p.z, zn[q], p.w)));
            bool v = act && (acc > sv[q]);
            unsigned msk = __ballot_sync(0xffffffffu, v);
            if (v) {
                int pos = cnt[q] + __popc(msk & ((1u << lane) - 1u));
                if (pos < CAP) nbr[w][q][pos] = m;
            }
            cnt[q] += __popc(msk);
        }
        __syncwarp();
    }

    // ---- Rare slow path: cnt > 32 -> keep 32 smallest original indices
    #pragma unroll
    for (int q = 0; q < QPW; q++) {
        if (cnt[q] > NSAMP) {
            int c = min(cnt[q], CAP);
            int v0 = (lane      < c) ? nbr[w][q][lane]      : 0x7fffffff;
            int v1 = (lane + 32 < c) ? nbr[w][q][lane + 32] : 0x7fffffff;
            for (int j = 0; j < NSAMP; j++) {
                int mn = min(v0, v1);
                #pragma unroll
                for (int d = 16; d >= 1; d >>= 1)
                    mn = min(mn, __shfl_xor_sync(0xffffffffu, mn, d));
                if (lane == 0) nbr[w][q][j] = mn;
                if (v0 == mn) v0 = 0x7fffffff;
                else if (v1 == mn) v1 = 0x7fffffff;
            }
            __syncwarp();
            cnt[q] = NSAMP;
        }
    }

    // ---- Per-lane MLP weights
    const float w1x = w1[3 * lane + 0];
    const float w1y = w1[3 * lane + 1];
    const float w1z = w1[3 * lane + 2];
    const float b1v = b1[lane];
    const unsigned long long bp = pk2(b2[lane], b2[lane + 32]);

    unsigned long long w2p[32];
    #pragma unroll
    for (int i = 0; i < 32; i++)
        w2p[i] = pk2(w2t[i * 65 + lane], w2t[i * 65 + lane + 32]);

    // ---- Phase 2: MLP + max pool; h staged to smem duplicated, f32x2 accumulate
    float2* hrow2 = (float2*)&hbuf[w][0];
    #pragma unroll
    for (int q = 0; q < QPW; q++) {
        const int k = cnt[q];                       // 1..32
        const float qx = xn[q], qy = yn[q], qz = zn[q];
        float p0 = 0.0f, p1 = 0.0f;
        for (int j0 = 0; j0 < k; j0 += JT) {
            const int je = min(k, j0 + JT);
            // Step A: compute h for tile neighbors, store duplicated (h,h)
            for (int j = j0; j < je; j++) {
                int m = nbr[w][q][j];
                float4 p = P[m];                    // uniform -> broadcast
                float rx = fmaf(0.5f, p.x, -qx);    // exact fl(x_m - x_n)
                float ry = fmaf(0.5f, p.y, -qy);
                float rz = fmaf(0.5f, p.z, -qz);
                float h = fmaf(w1x, rx, fmaf(w1y, ry, fmaf(w1z, rz, b1v)));
                h = fmaxf(h, 0.0f);
                hrow2[(j - j0) * 32 + lane] = make_float2(h, h);
            }
            __syncwarp();
            // Step B: 32 packed FMAs per neighbor via uniform LDS.128
            for (int j = j0; j < je; j++) {
                const ulonglong2* hr = (const ulonglong2*)&hbuf[w][(j - j0) * 64];
                unsigned long long acc = bp;
                #pragma unroll
                for (int i = 0; i < 16; i++) {
                    ulonglong2 hh = hr[i];
                    ffma2(acc, w2p[2 * i    ], hh.x);
                    ffma2(acc, w2p[2 * i + 1], hh.y);
                }
                float a0, a1;
                asm("mov.b64 {%0, %1}, %2;" : "=f"(a0), "=f"(a1) : "l"(acc));
                p0 = fmaxf(p0, fmaxf(a0, 0.0f));
                p1 = fmaxf(p1, fmaxf(a1, 0.0f));
            }
            __syncwarp();
        }
        float* o = out + (size_t)(b * NPTS + nbase + q) * 65;
        o[lane]      = p0;
        o[lane + 32] = p1;
        if (lane == 0) o[64] = (float)k * (1.0f / 64.0f);
    }
}

extern "C" void kernel_launch(void* const* d_in, const int* in_sizes, int n_in,
                              void* d_out, int out_size) {
    const float* xyz = (const float*)d_in[0];
    const float* w1  = (const float*)d_in[1];
    const float* b1  = (const float*)d_in[2];
    const float* w2  = (const float*)d_in[3];
    const float* b2  = (const float*)d_in[4];
    float* out = (float*)d_out;

    lse_zero   <<<(BATCH * GD3 + 255) / 256, 256>>>();
    lse_prep   <<<(BATCH * NPTS + 255) / 256, 256>>>(xyz);
    lse_alloc  <<<(BATCH * GD3 + 255) / 256, 256>>>();
    lse_scatter<<<(BATCH * NPTS + 255) / 256, 256>>>();
    lse_main_kernel<<<BATCH * (NPTS / (QPW * 16)), 512>>>(w1, b1, w2, b2, out);
}

// round 5
// speedup vs baseline: 1.8730x; 1.0478x over previous
#include <cuda_runtime.h>

#define NPTS   4096
#define BATCH  8
#define NSAMP  32
#define R2     0.0625f
#define QPW    4
#define GD     28
#define GD3    (GD*GD*GD)
#define CAP    64
#define JT     4
#define CPMAX  768

// Preprocessed points: (2x, 2y, 2z, -(x^2+y^2+z^2))
__device__ float4 xyz4g[BATCH * NPTS];
__device__ int    pointCell[BATCH * NPTS];
__device__ int    inCellOff[BATCH * NPTS];
__device__ int    cellCnt [BATCH * GD3];
__device__ int    cellStart[BATCH * GD3];
__device__ int    baseCtr[BATCH];
__device__ float4 sortedPts[BATCH * NPTS];   // cell-grouped point data
__device__ int    sortedIdxG[BATCH * NPTS];  // cell-grouped original indices

__device__ __forceinline__ int cellc(float v) {
    int c = (int)floorf((v + 3.5f) * 4.0f);
    return min(GD - 1, max(0, c));
}

__device__ __forceinline__ unsigned long long pk2(float lo, float hi) {
    unsigned long long r;
    asm("mov.b64 %0, {%1, %2};" : "=l"(r) : "f"(lo), "f"(hi));
    return r;
}
__device__ __forceinline__ void ffma2(unsigned long long& d,
                                      unsigned long long a, unsigned long long b) {
    asm("fma.rn.f32x2 %0, %1, %2, %0;" : "+l"(d) : "l"(a), "l"(b));
}

__global__ void lse_zero() {
    int i = blockIdx.x * blockDim.x + threadIdx.x;
    if (i < BATCH * GD3) cellCnt[i] = 0;
    if (i < BATCH) baseCtr[i] = 0;
}

__global__ void lse_prep(const float* __restrict__ xyz) {
    int i = blockIdx.x * blockDim.x + threadIdx.x;
    if (i >= BATCH * NPTS) return;
    float x = xyz[3*i], y = xyz[3*i+1], z = xyz[3*i+2];
    float sq = fmaf(x, x, fmaf(y, y, z * z));
    xyz4g[i] = make_float4(2.0f*x, 2.0f*y, 2.0f*z, -sq);
    int cid = (cellc(z) * GD + cellc(y)) * GD + cellc(x);
    pointCell[i] = cid;
    inCellOff[i] = atomicAdd(&cellCnt[(i >> 12) * GD3 + cid], 1);
}

// Parallel bump allocation: any disjoint per-cell layout is valid.
__global__ void lse_alloc() {
    int i = blockIdx.x * blockDim.x + threadIdx.x;
    if (i >= BATCH * GD3) return;
    int c = cellCnt[i];
    if (c > 0) cellStart[i] = atomicAdd(&baseCtr[i / GD3], c);
}

__global__ void lse_scatter() {
    int i = blockIdx.x * blockDim.x + threadIdx.x;
    if (i >= BATCH * NPTS) return;
    int b = i >> 12;
    int pos = cellStart[b * GD3 + pointCell[i]] + inCellOff[i];
    sortedPts [b * NPTS + pos] = xyz4g[i];
    sortedIdxG[b * NPTS + pos] = i & (NPTS - 1);
}

// 512 threads = 16 warps; each warp owns 4 query points.
__global__ __launch_bounds__(512, 1) void lse_main_kernel(
    const float* __restrict__ w1, const float* __restrict__ b1,
    const float* __restrict__ w2, const float* __restrict__ b2,
    float* __restrict__ out)
{
    __shared__ float  w2t[32 * 65];
    __shared__ float4 qp[16][QPW];                       // (xn,yn,zn,sv) per query
    __shared__ unsigned short nbrS[16][QPW][CAP];        // sorted positions
    __shared__ unsigned short cPos[16][CPMAX + 32];      // tagged candidate stream
    __shared__ __align__(16) float hbuf[16][JT * 64];    // duplicated h

    const int tid = threadIdx.x;
    for (int t = tid; t < 64 * 32; t += 512) {
        int o = t >> 5, i = t & 31;
        w2t[i * 65 + o] = w2[t];
    }
    __syncthreads();

    const int lane = tid & 31;
    const int w    = tid >> 5;
    const int b    = blockIdx.x >> 6;
    const int nbase = ((blockIdx.x & 63) << 6) + (w << 2);

    const float4* __restrict__ P    = xyz4g      + b * NPTS;
    const float4* __restrict__ SP   = sortedPts  + b * NPTS;
    const int*    __restrict__ SI   = sortedIdxG + b * NPTS;
    const int*    __restrict__ csG  = cellStart  + b * GD3;
    const int*    __restrict__ ccG  = cellCnt    + b * GD3;

    float xn[QPW], yn[QPW], zn[QPW], sv[QPW];
    int cnt0 = 0, cnt1 = 0, cnt2 = 0, cnt3 = 0;
    #pragma unroll
    for (int q = 0; q < QPW; q++) {
        float4 qn = P[nbase + q];
        xn[q] = 0.5f * qn.x;          // exact x_n
        yn[q] = 0.5f * qn.y;
        zn[q] = 0.5f * qn.z;
        sv[q] = -qn.w - R2;           // sq_n - R^2
        if (lane == 0) qp[w][q] = make_float4(xn[q], yn[q], zn[q], sv[q]);
    }

    const int dxl = lane % 3 - 1;
    const int dyl = (lane / 3) % 3 - 1;
    const int dzl = lane / 9 - 1;

    // ---- Phase 1a: expand 27-cell candidate ranges into one tagged stream
    int B = 0;
    #pragma unroll
    for (int q = 0; q < QPW; q++) {
        int gx = cellc(xn[q]) + dxl;
        int gy = cellc(yn[q]) + dyl;
        int gz = cellc(zn[q]) + dzl;
        bool cv = (lane < 27) & (gx >= 0) & (gx < GD) & (gy >= 0) & (gy < GD)
                              & (gz >= 0) & (gz < GD);
        int cs = 0, cc = 0;
        if (cv) {
            int cid = (gz * GD + gy) * GD + gx;
            cs = csG[cid];
            cc = ccG[cid];
        }
        int inc = cc;
        #pragma unroll
        for (int d = 1; d < 32; d <<= 1) {
            int u = __shfl_up_sync(0xffffffffu, inc, d);
            if (lane >= d) inc += u;
        }
        int base = B + (inc - cc);
        unsigned short tag0 = (unsigned short)((q << 12) | cs);
        for (int i = 0; i < cc; i++) {
            int idx = base + i;
            if (idx < CPMAX) cPos[w][idx] = tag0 + (unsigned short)i;
        }
        B += __shfl_sync(0xffffffffu, inc, 31);
    }
    const int T = min(B, CPMAX);
    __syncwarp();

    // ---- Phase 1b: single pipelined gather over all queries' candidates
    const unsigned below = (1u << lane) - 1u;
    for (int t0 = 0; t0 < T; t0 += 32) {
        int t = t0 + lane;
        bool act = t < T;
        int tag = cPos[w][t];             // array padded: in-bounds even if !act
        int q   = tag >> 12;
        int pos = tag & 0xFFF;
        float4 p = SP[pos];
        float4 Q = qp[w][q];
        float acc = fmaf(p.x, Q.x, fmaf(p.y, Q.y, fmaf(p.z, Q.z, p.w)));
        bool v = act && (acc > Q.w);
        #pragma unroll
        for (int qq = 0; qq < QPW; qq++) {
            unsigned msk = __ballot_sync(0xffffffffu, v && (q == qq));
            int& cq = (qq == 0) ? cnt0 : (qq == 1) ? cnt1 : (qq == 2) ? cnt2 : cnt3;
            if (v && q == qq) {
                int pn = cq + __popc(msk & below);
                if (pn < CAP) nbrS[w][qq][pn] = (unsigned short)pos;
            }
            cq += __popc(msk);
        }
    }
    __syncwarp();

    int cnt[QPW] = {cnt0, cnt1, cnt2, cnt3};

    // ---- Rare slow path: cnt > 32 -> keep 32 smallest ORIGINAL indices
    #pragma unroll
    for (int q = 0; q < QPW; q++) {
        if (cnt[q] > NSAMP) {                       // warp-uniform
            int c = min(cnt[q], CAP);
            int k0 = 0x7fffffff, k1 = 0x7fffffff;
            if (lane < c) {
                int pos = nbrS[w][q][lane];
                k0 = (SI[pos] << 12) | pos;         // unique keys
            }
            if (lane + 32 < c) {
                int pos = nbrS[w][q][lane + 32];
                k1 = (SI[pos] << 12) | pos;
            }
            for (int j = 0; j < NSAMP; j++) {
                int mn = min(k0, k1);
                #pragma unroll
                for (int d = 16; d >= 1; d >>= 1)
                    mn = min(mn, __shfl_xor_sync(0xffffffffu, mn, d));
                if (lane == 0) nbrS[w][q][j] = (unsigned short)(mn & 0xFFF);
                if (k0 == mn) k0 = 0x7fffffff;
                else if (k1 == mn) k1 = 0x7fffffff;
            }
            __syncwarp();
            cnt[q] = NSAMP;
        }
    }

    // ---- Per-lane MLP weights
    const float w1x = w1[3 * lane + 0];
    const float w1y = w1[3 * lane + 1];
    const float w1z = w1[3 * lane + 2];
    const float b1v = b1[lane];
    const unsigned long long bp = pk2(b2[lane], b2[lane + 32]);

    unsigned long long w2p[32];
    #pragma unroll
    for (int i = 0; i < 32; i++)
        w2p[i] = pk2(w2t[i * 65 + lane], w2t[i * 65 + lane + 32]);

    // ---- Phase 2: MLP + max pool; h staged duplicated, f32x2 accumulate
    float2* hrow2 = (float2*)&hbuf[w][0];
    #pragma unroll
    for (int q = 0; q < QPW; q++) {
        const int k = cnt[q];                       // 1..32
        const float qx = xn[q], qy = yn[q], qz = zn[q];
        float p0 = 0.0f, p1 = 0.0f;
        for (int j0 = 0; j0 < k; j0 += JT) {
            const int je = min(k, j0 + JT);
            for (int j = j0; j < je; j++) {
                int pos = nbrS[w][q][j];
                float4 p = SP[pos];                 // uniform -> broadcast
                float rx = fmaf(0.5f, p.x, -qx);    // exact fl(x_m - x_n)
                float ry = fmaf(0.5f, p.y, -qy);
                float rz = fmaf(0.5f, p.z, -qz);
                float h = fmaf(w1x, rx, fmaf(w1y, ry, fmaf(w1z, rz, b1v)));
                h = fmaxf(h, 0.0f);
                hrow2[(j - j0) * 32 + lane] = make_float2(h, h);
            }
            __syncwarp();
            for (int j = j0; j < je; j++) {
                const ulonglong2* hr = (const ulonglong2*)&hbuf[w][(j - j0) * 64];
                unsigned long long acc = bp;
                #pragma unroll
                for (int i = 0; i < 16; i++) {
                    ulonglong2 hh = hr[i];
                    ffma2(acc, w2p[2 * i    ], hh.x);
                    ffma2(acc, w2p[2 * i + 1], hh.y);
                }
                float a0, a1;
                asm("mov.b64 {%0, %1}, %2;" : "=f"(a0), "=f"(a1) : "l"(acc));
                p0 = fmaxf(p0, fmaxf(a0, 0.0f));
                p1 = fmaxf(p1, fmaxf(a1, 0.0f));
            }
            __syncwarp();
        }
        float* o = out + (size_t)(b * NPTS + nbase + q) * 65;
        o[lane]      = p0;
        o[lane + 32] = p1;
        if (lane == 0) o[64] = (float)k * (1.0f / 64.0f);
    }
}

extern "C" void kernel_launch(void* const* d_in, const int* in_sizes, int n_in,
                              void* d_out, int out_size) {
    const float* xyz = (const float*)d_in[0];
    const float* w1  = (const float*)d_in[1];
    const float* b1  = (const float*)d_in[2];
    const float* w2  = (const float*)d_in[3];
    const float* b2  = (const float*)d_in[4];
    float* out = (float*)d_out;

    lse_zero   <<<(BATCH * GD3 + 255) / 256, 256>>>();
    lse_prep   <<<(BATCH * NPTS + 255) / 256, 256>>>(xyz);
    lse_alloc  <<<(BATCH * GD3 + 255) / 256, 256>>>();
    lse_scatter<<<(BATCH * NPTS + 255) / 256, 256>>>();
    lse_main_kernel<<<BATCH * (NPTS / (QPW * 16)), 512>>>(w1, b1, w2, b2, out);
}

// round 6
// speedup vs baseline: 2.0892x; 1.1154x over previous
#include <cuda_runtime.h>

#define NPTS   4096
#define BATCH  8
#define NSAMP  32
#define R2     0.0625f
#define QPW    4
#define GD     28
#define GD3    (GD*GD*GD)
#define CAP    64
#define JT     4
#define CPMAX  768
#define NITEMS (BATCH * NPTS / QPW)   // 8192
#define BGRID  128
#define BTHR   256
#define MGRID  148

__device__ float4 xyz4g[BATCH * NPTS];
__device__ int    pointCell[BATCH * NPTS];
__device__ int    inCellOff[BATCH * NPTS];
__device__ int    cellCnt [BATCH * GD3];
__device__ int    cellStart[BATCH * GD3];
__device__ int    baseCtr[BATCH];
__device__ float4 sortedPts[BATCH * NPTS];
__device__ int    sortedIdxG[BATCH * NPTS];
__device__ int    barCnt[3];
__device__ int    ticket;

__device__ __forceinline__ int cellc(float v) {
    int c = (int)floorf((v + 3.5f) * 4.0f);
    return min(GD - 1, max(0, c));
}

__device__ __forceinline__ unsigned long long pk2(float lo, float hi) {
    unsigned long long r;
    asm("mov.b64 %0, {%1, %2};" : "=l"(r) : "f"(lo), "f"(hi));
    return r;
}
__device__ __forceinline__ void ffma2(unsigned long long& d,
                                      unsigned long long a, unsigned long long b) {
    asm("fma.rn.f32x2 %0, %1, %2, %0;" : "+l"(d) : "l"(a), "l"(b));
}
__device__ __forceinline__ void fadd2(unsigned long long& d, unsigned long long a) {
    asm("add.rn.f32x2 %0, %0, %1;" : "+l"(d) : "l"(a));
}

__device__ __forceinline__ void gridbar(int idx) {
    __syncthreads();
    if (threadIdx.x == 0) {
        __threadfence();
        atomicAdd(&barCnt[idx], 1);
        while (atomicAdd(&barCnt[idx], 0) < BGRID) {}
        __threadfence();
    }
    __syncthreads();
}

// Fused grid build: zero -> histogram -> alloc -> scatter, with soft grid barriers.
// All 128 CTAs (256 thr, 0 smem) are guaranteed co-resident.
__global__ __launch_bounds__(BTHR) void lse_build(const float* __restrict__ xyz) {
    const int g = blockIdx.x * BTHR + threadIdx.x;   // 0..32767, one per point

    // phase 0: zero counters
    if (g == 0) ticket = 0;
    if (g < BATCH) baseCtr[g] = 0;
    for (int i = g; i < BATCH * GD3; i += BGRID * BTHR) cellCnt[i] = 0;
    gridbar(0);

    // phase 1: prep + histogram (one point per thread)
    {
        float x = xyz[3*g], y = xyz[3*g+1], z = xyz[3*g+2];
        float sq = fmaf(x, x, fmaf(y, y, z * z));
        xyz4g[g] = make_float4(2.0f*x, 2.0f*y, 2.0f*z, -sq);
        int cid = (cellc(z) * GD + cellc(y)) * GD + cellc(x);
        pointCell[g] = cid;
        inCellOff[g] = atomicAdd(&cellCnt[(g >> 12) * GD3 + cid], 1);
    }
    gridbar(1);

    // phase 2: bump allocation (any disjoint layout is valid)
    for (int i = g; i < BATCH * GD3; i += BGRID * BTHR) {
        int c = cellCnt[i];
        if (c > 0) cellStart[i] = atomicAdd(&baseCtr[i / GD3], c);
    }
    gridbar(2);

    // phase 3: scatter
    {
        int b = g >> 12;
        int pos = cellStart[b * GD3 + pointCell[g]] + inCellOff[g];
        sortedPts [b * NPTS + pos] = xyz4g[g];
        sortedIdxG[b * NPTS + pos] = g & (NPTS - 1);
    }
}

// Persistent main kernel: 148 CTAs x 512 thr; warps steal 4-query items.
__global__ __launch_bounds__(512, 1) void lse_main_kernel(
    const float* __restrict__ w1, const float* __restrict__ b1,
    const float* __restrict__ w2, const float* __restrict__ b2,
    float* __restrict__ out)
{
    __shared__ float  w2t[32 * 65];
    __shared__ float4 qp[16][QPW];
    __shared__ unsigned short nbrS[16][QPW][CAP];
    __shared__ unsigned short cPos[16][CPMAX + 32];
    __shared__ __align__(16) float hbuf[16][JT * 64];

    const int tid = threadIdx.x;
    // reset build-kernel barriers for the next launch (stream-ordered after build)
    if (blockIdx.x == 0 && tid < 3) barCnt[tid] = 0;

    for (int t = tid; t < 64 * 32; t += 512) {
        int o = t >> 5, i = t & 31;
        w2t[i * 65 + o] = w2[t];
    }
    __syncthreads();

    const int lane = tid & 31;
    const int w    = tid >> 5;
    const unsigned below = (1u << lane) - 1u;

    const int dxl = lane % 3 - 1;
    const int dyl = (lane / 3) % 3 - 1;
    const int dzl = lane / 9 - 1;

    // Per-lane MLP weights (live whole kernel)
    const float w1x = w1[3 * lane + 0];
    const float w1y = w1[3 * lane + 1];
    const float w1z = w1[3 * lane + 2];
    const float b1v = b1[lane];
    const unsigned long long bp = pk2(b2[lane], b2[lane + 32]);
    const unsigned long long zz = pk2(0.0f, 0.0f);

    unsigned long long w2p[32];
    #pragma unroll
    for (int i = 0; i < 32; i++)
        w2p[i] = pk2(w2t[i * 65 + lane], w2t[i * 65 + lane + 32]);

    for (;;) {
        int item;
        if (lane == 0) item = atomicAdd(&ticket, 1);
        item = __shfl_sync(0xffffffffu, item, 0);
        if (item >= NITEMS) break;
        const int b     = item >> 10;
        const int nbase = (item & 1023) << 2;

        const float4* __restrict__ P   = xyz4g      + b * NPTS;
        const float4* __restrict__ SP  = sortedPts  + b * NPTS;
        const int*    __restrict__ SI  = sortedIdxG + b * NPTS;
        const int*    __restrict__ csG = cellStart  + b * GD3;
        const int*    __restrict__ ccG = cellCnt    + b * GD3;

        float xn[QPW], yn[QPW], zn[QPW], sv[QPW];
        int cnt0 = 0, cnt1 = 0, cnt2 = 0, cnt3 = 0;
        #pragma unroll
        for (int q = 0; q < QPW; q++) {
            float4 qn = P[nbase + q];
            xn[q] = 0.5f * qn.x;
            yn[q] = 0.5f * qn.y;
            zn[q] = 0.5f * qn.z;
            sv[q] = -qn.w - R2;
            if (lane == 0) qp[w][q] = make_float4(xn[q], yn[q], zn[q], sv[q]);
        }

        // ---- Phase 1a: expand 27-cell ranges into one tagged candidate stream
        int B = 0;
        #pragma unroll
        for (int q = 0; q < QPW; q++) {
            int gx = cellc(xn[q]) + dxl;
            int gy = cellc(yn[q]) + dyl;
            int gz = cellc(zn[q]) + dzl;
            bool cv = (lane < 27) & (gx >= 0) & (gx < GD) & (gy >= 0) & (gy < GD)
                                  & (gz >= 0) & (gz < GD);
            int cs = 0, cc = 0;
            if (cv) {
                int cid = (gz * GD + gy) * GD + gx;
                cs = csG[cid];
                cc = ccG[cid];
            }
            int inc = cc;
            #pragma unroll
            for (int d = 1; d < 32; d <<= 1) {
                int u = __shfl_up_sync(0xffffffffu, inc, d);
                if (lane >= d) inc += u;
            }
            int base = B + (inc - cc);
            unsigned short tag0 = (unsigned short)((q << 12) | cs);
            for (int i = 0; i < cc; i++) {
                int idx = base + i;
                if (idx < CPMAX) cPos[w][idx] = tag0 + (unsigned short)i;
            }
            B += __shfl_sync(0xffffffffu, inc, 31);
        }
        const int T = min(B, CPMAX);
        __syncwarp();

        // ---- Phase 1b: pipelined gather over all 4 queries' candidates
        #pragma unroll 2
        for (int t0 = 0; t0 < T; t0 += 32) {
            int t = t0 + lane;
            bool act = t < T;
            int tag = cPos[w][t];
            int q   = tag >> 12;
            int pos = tag & 0xFFF;
            float4 p = SP[pos];
            float4 Q = qp[w][q];
            float acc = fmaf(p.x, Q.x, fmaf(p.y, Q.y, fmaf(p.z, Q.z, p.w)));
            bool v = act && (acc > Q.w);
            #pragma unroll
            for (int qq = 0; qq < QPW; qq++) {
                unsigned msk = __ballot_sync(0xffffffffu, v && (q == qq));
                int& cq = (qq == 0) ? cnt0 : (qq == 1) ? cnt1 : (qq == 2) ? cnt2 : cnt3;
                if (v && q == qq) {
                    int pn = cq + __popc(msk & below);
                    if (pn < CAP) nbrS[w][qq][pn] = (unsigned short)pos;
                }
                cq += __popc(msk);
            }
        }
        __syncwarp();

        int cnt[QPW] = {cnt0, cnt1, cnt2, cnt3};

        // ---- Rare slow path: cnt > 32 -> keep 32 smallest ORIGINAL indices
        #pragma unroll
        for (int q = 0; q < QPW; q++) {
            if (cnt[q] > NSAMP) {
                int c = min(cnt[q], CAP);
                int k0 = 0x7fffffff, k1 = 0x7fffffff;
                if (lane < c) {
                    int pos = nbrS[w][q][lane];
                    k0 = (SI[pos] << 12) | pos;
                }
                if (lane + 32 < c) {
                    int pos = nbrS[w][q][lane + 32];
                    k1 = (SI[pos] << 12) | pos;
                }
                for (int j = 0; j < NSAMP; j++) {
                    int mn = min(k0, k1);
                    #pragma unroll
                    for (int d = 16; d >= 1; d >>= 1)
                        mn = min(mn, __shfl_xor_sync(0xffffffffu, mn, d));
                    if (lane == 0) nbrS[w][q][j] = (unsigned short)(mn & 0xFFF);
                    if (k0 == mn) k0 = 0x7fffffff;
                    else if (k1 == mn) k1 = 0x7fffffff;
                }
                __syncwarp();
                cnt[q] = NSAMP;
            }
        }

        // ---- Phase 2: MLP + max pool; prefetched tiles, 4-way split accumulators
        float2* hrow2 = (float2*)&hbuf[w][0];
        #pragma unroll
        for (int q = 0; q < QPW; q++) {
            const int k = cnt[q];                       // 1..32
            const float qx = xn[q], qy = yn[q], qz = zn[q];
            float p0 = 0.0f, p1 = 0.0f;
            for (int j0 = 0; j0 < k; j0 += JT) {
                const int je = min(k, j0 + JT);
                // A: independent position LDS + point LDGs, then h compute
                int   posj[JT];
                float4 pv[JT];
                #pragma unroll
                for (int jj = 0; jj < JT; jj++)
                    posj[jj] = nbrS[w][q][min(j0 + jj, k - 1)];
                #pragma unroll
                for (int jj = 0; jj < JT; jj++)
                    pv[jj] = SP[posj[jj]];
                #pragma unroll
                for (int jj = 0; jj < JT; jj++) {
                    if (j0 + jj < je) {
                        float rx = fmaf(0.5f, pv[jj].x, -qx);
                        float ry = fmaf(0.5f, pv[jj].y, -qy);
                        float rz = fmaf(0.5f, pv[jj].z, -qz);
                        float h = fmaf(w1x, rx, fmaf(w1y, ry, fmaf(w1z, rz, b1v)));
                        h = fmaxf(h, 0.0f);
                        hrow2[jj * 32 + lane] = make_float2(h, h);
                    }
                }
                __syncwarp();
                // B: 32 packed FMAs in 4 independent chains per neighbor
                #pragma unroll
                for (int jj = 0; jj < JT; jj++) {
                    if (j0 + jj < je) {
                        const ulonglong2* hr = (const ulonglong2*)&hbuf[w][jj * 64];
                        unsigned long long a0 = bp, a1 = zz, a2 = zz, a3 = zz;
                        #pragma unroll
                        for (int i = 0; i < 4; i++) {
                            ulonglong2 h0 = hr[4 * i    ];
                            ulonglong2 h1 = hr[4 * i + 1];
                            ulonglong2 h2 = hr[4 * i + 2];
                            ulonglong2 h3 = hr[4 * i + 3];
                            ffma2(a0, w2p[8 * i    ], h0.x);
                            ffma2(a1, w2p[8 * i + 1], h0.y);
                            ffma2(a2, w2p[8 * i + 2], h1.x);
                            ffma2(a3, w2p[8 * i + 3], h1.y);
                            ffma2(a0, w2p[8 * i + 4], h2.x);
                            ffma2(a1, w2p[8 * i + 5], h2.y);
                            ffma2(a2, w2p[8 * i + 6], h3.x);
                            ffma2(a3, w2p[8 * i + 7], h3.y);
                        }
                        fadd2(a0, a1);
                        fadd2(a2, a3);
                        fadd2(a0, a2);
                        float r0, r1;
                        asm("mov.b64 {%0, %1}, %2;" : "=f"(r0), "=f"(r1) : "l"(a0));
                        p0 = fmaxf(p0, fmaxf(r0, 0.0f));
                        p1 = fmaxf(p1, fmaxf(r1, 0.0f));
                    }
                }
                __syncwarp();
            }
            float* o = out + (size_t)(b * NPTS + nbase + q) * 65;
            o[lane]      = p0;
            o[lane + 32] = p1;
            if (lane == 0) o[64] = (float)k * (1.0f / 64.0f);
        }
    }
}

extern "C" void kernel_launch(void* const* d_in, const int* in_sizes, int n_in,
                              void* d_out, int out_size) {
    const float* xyz = (const float*)d_in[0];
    const float* w1  = (const float*)d_in[1];
    const float* b1  = (const float*)d_in[2];
    const float* w2  = (const float*)d_in[3];
    const float* b2  = (const float*)d_in[4];
    float* out = (float*)d_out;

    lse_build<<<BGRID, BTHR>>>(xyz);
    lse_main_kernel<<<MGRID, 512>>>(w1, b1, w2, b2, out);
}